// round 11
// baseline (speedup 1.0000x reference)
#include <cuda_runtime.h>
#include <cstdint>

#define NLEV 5
#define BATCH 128
#define NBOX 64

static __constant__ int c_Hc[NLEV] = {334, 167, 84, 42, 21};
static __constant__ int c_Wc[NLEV] = {200, 100, 50, 25, 13};

// float4 counts per level: (128*H*W)/4
#define N4_0 2137600
#define N4_1 534400
#define N4_2 134400
#define N4_3 33600
#define N4_4 8736

// Sum phase (round-8 champion): 10 unrolled lane-loads * 32 lanes per warp.
#define ULOADS 10
#define WARP_SPAN (32 * ULOADS)
#define WS0 0
#define WS1 6680
#define WS2 8350
#define WS3 8770
#define WS4 8875
#define WSE 8903

// Count blocks: level 0 split into 2 half-height blocks per batch.
//   blocks [0, 256)   : level 0, b = bx>>1, half = bx&1  (167 rows each)
//   blocks [256, 768) : levels 1-4, one (lev,b) each
#define CNT_BLOCKS   768
#define TOTAL_BLOCKS 1184             // one full wave at 8 blocks/SM
#define THREADS      256
#define NWARP        (THREADS / 32)
#define PS_W         296              // TOTAL_BLOCKS/4 float4 per level

__device__ float4       p_sum4[NLEV][PS_W];   // per-level per-block partials
__device__ uint4        p_cnt4[CNT_BLOCKS / 4];
__device__ unsigned int g_done;   // zero at load; reset by last block

// ---------------------------------------------------------------------------
template <typename T>
__device__ __forceinline__ T block_reduce_sum(T val) {
    __shared__ T sh[32];
    int lane = threadIdx.x & 31;
    int wid  = threadIdx.x >> 5;
#pragma unroll
    for (int o = 16; o > 0; o >>= 1) val += __shfl_down_sync(0xffffffffu, val, o);
    if (lane == 0) sh[wid] = val;
    __syncthreads();
    T r = (threadIdx.x < (unsigned)NWARP) ? sh[lane] : T(0);
    if (wid == 0) {
#pragma unroll
        for (int o = 16; o > 0; o >>= 1) r += __shfl_down_sync(0xffffffffu, r, o);
    }
    __syncthreads();
    return r;
}

// ---------------------------------------------------------------------------
// Count rows [row0, row0+HB) of one (level, batch).
// Box threads place 2 atomicXor toggles; row activity recovered by a 2-level
// XOR prefix-scan across threads (one row per thread, HB <= THREADS).
// sb (u32): x-masks [64*STRIDE] | toggles lo[HB] | toggles hi[HB]
// ---------------------------------------------------------------------------
template <int H, int W, int HB>
__device__ __forceinline__ unsigned int do_count_rows(
    const float* __restrict__ boxes, int b, int row0, unsigned int* sb) {
    constexpr int   NW     = (W + 31) / 32;
    constexpr int   STRIDE = (NW | 1);
    constexpr float sx     = (float)(W / 800.0);
    constexpr float sy     = (float)(H / 1333.0);
    constexpr int   row1   = 0;  // placeholder to keep template simple
    (void)row1;

    unsigned int* s_xm = sb;
    unsigned int* s_lo = sb + NBOX * STRIDE;
    unsigned int* s_hi = s_lo + HB;
    __shared__ unsigned int s_wc_lo[NWARP], s_wc_hi[NWARP];

    int tid  = threadIdx.x;
    int lane = tid & 31;
    int wid  = tid >> 5;
    int rend = row0 + HB;

    for (int i = tid; i < 2 * HB; i += THREADS) s_lo[i] = 0u;
    __syncthreads();

    if (tid < NBOX) {
        const float* bp = boxes + ((size_t)b * NBOX + tid) * 4;
        float fx1 = fminf(fmaxf(rintf(bp[0] * sx), 0.0f), (float)(W - 1));
        float fy1 = fminf(fmaxf(rintf(bp[1] * sy), 0.0f), (float)(H - 1));
        float fx2 = fminf(fmaxf(rintf(bp[2] * sx), 0.0f), (float)W);
        float fy2 = fminf(fmaxf(rintf(bp[3] * sy), 0.0f), (float)H);
        int ix1 = (int)fx1, iy1 = (int)fy1, ix2 = (int)fx2, iy2 = (int)fy2;
        bool valid = (fx2 > fx1) && (fy2 > fy1);

#pragma unroll
        for (int wi = 0; wi < NW; wi++) {
            int lo = ix1 - wi * 32;
            int hi = ix2 - wi * 32;
            lo = lo < 0 ? 0 : lo;
            hi = hi > 32 ? 32 : hi;
            unsigned int wmask = 0u;
            if (hi > lo) {
                unsigned int hm = (hi == 32) ? 0xFFFFFFFFu : ((1u << hi) - 1u);
                wmask = hm & (0xFFFFFFFFu << lo);
            }
            s_xm[tid * STRIDE + wi] = wmask;
        }

        // toggle events clipped to this block's row range
        int ya = iy1 < row0 ? row0 : iy1;
        int yb = iy2 > rend ? rend : iy2;
        if (valid && ya < yb) {
            unsigned int  bit = 1u << (tid & 31);
            unsigned int* tgt = (tid < 32) ? s_lo : s_hi;
            atomicXor(&tgt[ya - row0], bit);
            if (yb < rend) atomicXor(&tgt[yb - row0], bit);
        }
    }
    __syncthreads();

    // inclusive XOR prefix scan across threads (rows)
    unsigned int tlo = (tid < HB) ? s_lo[tid] : 0u;
    unsigned int thi = (tid < HB) ? s_hi[tid] : 0u;
#pragma unroll
    for (int o = 1; o < 32; o <<= 1) {
        unsigned int vlo = __shfl_up_sync(0xffffffffu, tlo, o);
        unsigned int vhi = __shfl_up_sync(0xffffffffu, thi, o);
        if (lane >= o) { tlo ^= vlo; thi ^= vhi; }
    }
    if (lane == 31) { s_wc_lo[wid] = tlo; s_wc_hi[wid] = thi; }
    __syncthreads();
    unsigned int clo = 0u, chi = 0u;
#pragma unroll
    for (int j = 0; j < NWARP - 1; j++) {
        if (j < wid) { clo ^= s_wc_lo[j]; chi ^= s_wc_hi[j]; }
    }
    unsigned int mlo = tlo ^ clo;
    unsigned int mhi = thi ^ chi;

    unsigned int cnt = 0;
    if (tid < HB) {
        unsigned int w[NW];
#pragma unroll
        for (int wi = 0; wi < NW; wi++) w[wi] = 0u;
        while (mlo) {
            int m = __ffs(mlo) - 1;
            mlo &= mlo - 1;
            const unsigned int* bm = &s_xm[m * STRIDE];
#pragma unroll
            for (int wi = 0; wi < NW; wi++) w[wi] |= bm[wi];
        }
        while (mhi) {
            int m = __ffs(mhi) - 1 + 32;
            mhi &= mhi - 1;
            const unsigned int* bm = &s_xm[m * STRIDE];
#pragma unroll
            for (int wi = 0; wi < NW; wi++) w[wi] |= bm[wi];
        }
#pragma unroll
        for (int wi = 0; wi < NW; wi++) cnt += (unsigned)__popc(w[wi]);
    }
    __syncthreads();
    return cnt;
}

// shared scratch: 64*7 + 2*167 = 782 u32
__device__ __forceinline__ unsigned int* cnt_smem() {
    static __shared__ unsigned int buf[800];
    return buf;
}

// ---------------------------------------------------------------------------
__global__ void __launch_bounds__(THREADS, 8)
work_kernel(const float* __restrict__ h0, const float* __restrict__ h1,
            const float* __restrict__ h2, const float* __restrict__ h3,
            const float* __restrict__ h4, const float* __restrict__ boxes,
            float* __restrict__ out) {
    int bx   = blockIdx.x;
    int tid  = threadIdx.x;
    int lane = tid & 31;
    int wid  = tid >> 5;

    // ============ sum phase: static contiguous per-warp partition ==========
    __shared__ float s_wsum[NWARP];
    __shared__ int   s_wlev[NWARP];
    {
        int g = bx * NWARP + wid;      // global warp id
        float s = 0.0f;
        int lev = -1;
        if (g < WSE) {
            lev = (g < WS1) ? 0 : (g < WS2) ? 1 : (g < WS3) ? 2
                : (g < WS4) ? 3 : 4;
            const float* hp = (lev == 0) ? h0 : (lev == 1) ? h1
                            : (lev == 2) ? h2 : (lev == 3) ? h3 : h4;
            int start = (lev == 0) ? WS0 : (lev == 1) ? WS1
                      : (lev == 2) ? WS2 : (lev == 3) ? WS3 : WS4;
            int n4    = (lev == 0) ? N4_0 : (lev == 1) ? N4_1
                      : (lev == 2) ? N4_2 : (lev == 3) ? N4_3 : N4_4;
            const float4* p = reinterpret_cast<const float4*>(hp);
            int idx0 = (g - start) * WARP_SPAN + lane;
            float a0 = 0.0f, a1 = 0.0f, a2 = 0.0f, a3 = 0.0f;
#pragma unroll
            for (int u = 0; u < ULOADS; u += 2) {
                int i0 = idx0 + u * 32;
                int i1 = idx0 + (u + 1) * 32;
                float4 v0 = (i0 < n4) ? p[i0] : make_float4(0.f, 0.f, 0.f, 0.f);
                float4 v1 = (i1 < n4) ? p[i1] : make_float4(0.f, 0.f, 0.f, 0.f);
                a0 += v0.x + v0.y;
                a1 += v0.z + v0.w;
                a2 += v1.x + v1.y;
                a3 += v1.z + v1.w;
            }
            s = (a0 + a1) + (a2 + a3);
#pragma unroll
            for (int o = 16; o > 0; o >>= 1)
                s += __shfl_down_sync(0xffffffffu, s, o);
        }
        if (lane == 0) { s_wsum[wid] = s; s_wlev[wid] = lev; }
        __syncthreads();
        if (tid == 0) {
            float acc0 = 0.f, acc1 = 0.f, acc2 = 0.f, acc3 = 0.f, acc4 = 0.f;
#pragma unroll
            for (int w2 = 0; w2 < NWARP; w2++) {
                int   l = s_wlev[w2];
                float v = s_wsum[w2];
                acc0 += (l == 0) ? v : 0.f;
                acc1 += (l == 1) ? v : 0.f;
                acc2 += (l == 2) ? v : 0.f;
                acc3 += (l == 3) ? v : 0.f;
                acc4 += (l == 4) ? v : 0.f;
            }
            float* ps = reinterpret_cast<float*>(&p_sum4[0][0]);
            ps[0 * TOTAL_BLOCKS + bx] = acc0;
            ps[1 * TOTAL_BLOCKS + bx] = acc1;
            ps[2 * TOTAL_BLOCKS + bx] = acc2;
            ps[3 * TOTAL_BLOCKS + bx] = acc3;
            ps[4 * TOTAL_BLOCKS + bx] = acc4;
        }
        __syncthreads();
    }

    // ============ count phase: blocks [0, 768) =============================
    if (bx < CNT_BLOCKS) {
        unsigned int* sb = cnt_smem();
        unsigned int cnt;
        if (bx < 256) {
            int b    = bx >> 1;
            int half = bx & 1;
            cnt = do_count_rows<334, 200, 167>(boxes, b, half ? 167 : 0, sb);
        } else {
            int t   = bx - 256;
            int lev = 1 + (t >> 7);
            int b   = t & 127;
            switch (lev) {
                case 1:  cnt = do_count_rows<167, 100, 167>(boxes, b, 0, sb); break;
                case 2:  cnt = do_count_rows<84, 50, 84>(boxes, b, 0, sb);    break;
                case 3:  cnt = do_count_rows<42, 25, 42>(boxes, b, 0, sb);    break;
                default: cnt = do_count_rows<21, 13, 21>(boxes, b, 0, sb);    break;
            }
        }
        cnt = block_reduce_sum<unsigned int>(cnt);
        if (tid == 0)
            reinterpret_cast<unsigned int*>(&p_cnt4[0])[bx] = cnt;
    }

    // ============ completion ticket -> finalize ============================
    __shared__ bool is_last;
    __threadfence();
    if (tid == 0) {
        unsigned int v = atomicAdd(&g_done, 1u);
        is_last = (v == TOTAL_BLOCKS - 1);
    }
    __syncthreads();
    if (!is_last) return;
    __threadfence();

    // 5 warps, vectorized partial loads (float4 / uint4)
    __shared__ double s_d2[NLEV];
    if (wid < NLEV) {
        int lev = wid;
        double s = 0.0;
        for (int i = lane; i < PS_W; i += 32) {
            float4 v = p_sum4[lev][i];
            s += (double)((v.x + v.y) + (v.z + v.w));
        }
        unsigned int c = 0;
        if (lev == 0) {
            for (int i = lane; i < 64; i += 32) {        // counts [0,256)
                uint4 v = p_cnt4[i];
                c += v.x + v.y + v.z + v.w;
            }
        } else {
            int base = 64 + (lev - 1) * 32;              // counts [256+...,+128)
            if (lane < 32) {
                uint4 v = p_cnt4[base + lane];
                c += v.x + v.y + v.z + v.w;
            }
        }
#pragma unroll
        for (int o = 16; o > 0; o >>= 1) {
            s += __shfl_down_sync(0xffffffffu, s, o);
            c += __shfl_down_sync(0xffffffffu, c, o);
        }
        if (lane == 0) {
            double tn = (double)BATCH * (double)c_Hc[lev] * (double)c_Wc[lev];
            double d  = s / tn - (double)c / tn;
            s_d2[lev] = d * d;
        }
    }
    __syncthreads();
    if (tid == 0) {
        double acc = s_d2[0] + s_d2[1] + s_d2[2] + s_d2[3] + s_d2[4];
        out[0] = (float)(acc / (double)NLEV);
        atomicExch(&g_done, 0u);
    }
}

// ---------------------------------------------------------------------------
extern "C" void kernel_launch(void* const* d_in, const int* in_sizes, int n_in,
                              void* d_out, int out_size) {
    (void)in_sizes; (void)n_in; (void)out_size;
    const float* h0    = (const float*)d_in[0];
    const float* h1    = (const float*)d_in[1];
    const float* h2    = (const float*)d_in[2];
    const float* h3    = (const float*)d_in[3];
    const float* h4    = (const float*)d_in[4];
    const float* boxes = (const float*)d_in[5];
    float* out = (float*)d_out;

    work_kernel<<<TOTAL_BLOCKS, THREADS>>>(h0, h1, h2, h3, h4, boxes, out);
}

// round 13
// speedup vs baseline: 1.2400x; 1.2400x over previous
#include <cuda_runtime.h>
#include <cstdint>

#define NLEV 5
#define BATCH 128
#define NBOX 64

static __constant__ int c_Hc[NLEV] = {334, 167, 84, 42, 21};
static __constant__ int c_Wc[NLEV] = {200, 100, 50, 25, 13};

// float4 counts per level: (128*H*W)/4
#define N4_0 2137600
#define N4_1 534400
#define N4_2 134400
#define N4_3 33600
#define N4_4 8736

// Sum warps: span 384 float4/warp (12 lane-loads), per-level warp ranges.
#define ULOADS 12
#define SPAN   384
#define WS0 0
#define WS1 5567
#define WS2 6959
#define WS3 7309
#define WS4 7397
#define WSE 7420

// Count blocks: level 0 split into 2 half-height tasks per batch.
//   blocks [0, 256)   : level 0, b = bx>>1, half = bx&1 (167 rows each)
//   blocks [256, 768) : levels 1-4, one (lev,b) each
#define CNT_BLOCKS   768
#define TOTAL_BLOCKS 1184            // one full wave at 8 blocks/SM
#define THREADS      256
#define NWARP        8
#define PS_W         296             // TOTAL_BLOCKS/4 float4 per level
// sum warps per count block = 6 -> pure-block warp-id base:
#define PURE_G_BASE  (CNT_BLOCKS * 6)   // 4608

__device__ float4       p_sum4[NLEV][PS_W];
__device__ uint4        p_cnt4[CNT_BLOCKS / 4];
__device__ unsigned int g_done;   // zero at load; reset by last block

// ---------------------------------------------------------------------------
// Count setup (warps 6-7 only, 64 threads): per-box x-masks + row marking.
// sb (u32): x-masks [64*STRIDE] | act_lo[HB] | act_hi[HB]
// ---------------------------------------------------------------------------
template <int H, int W, int HB>
__device__ __forceinline__ void count_setup(const float4* __restrict__ boxes4,
                                            int b, int row0, unsigned int* sb) {
    constexpr int   NW     = (W + 31) / 32;
    constexpr int   STRIDE = (NW | 1);
    constexpr float sx     = (float)(W / 800.0);
    constexpr float sy     = (float)(H / 1333.0);

    unsigned int* s_xm = sb;
    unsigned int* s_lo = sb + NBOX * STRIDE;
    unsigned int* s_hi = s_lo + HB;
    int ctid = threadIdx.x - 192;            // 0..63

    for (int i = ctid; i < 2 * HB; i += 64) s_lo[i] = 0u;
    asm volatile("bar.sync 1, 64;" ::: "memory");   // warps 6+7 only

    float4 bp = boxes4[b * NBOX + ctid];
    float fx1 = fminf(fmaxf(rintf(bp.x * sx), 0.0f), (float)(W - 1));
    float fy1 = fminf(fmaxf(rintf(bp.y * sy), 0.0f), (float)(H - 1));
    float fx2 = fminf(fmaxf(rintf(bp.z * sx), 0.0f), (float)W);
    float fy2 = fminf(fmaxf(rintf(bp.w * sy), 0.0f), (float)H);
    int ix1 = (int)fx1, iy1 = (int)fy1, ix2 = (int)fx2, iy2 = (int)fy2;
    bool valid = (fx2 > fx1) && (fy2 > fy1);

#pragma unroll
    for (int wi = 0; wi < NW; wi++) {
        int lo = ix1 - wi * 32;
        int hi = ix2 - wi * 32;
        lo = lo < 0 ? 0 : lo;
        hi = hi > 32 ? 32 : hi;
        unsigned int wmask = 0u;
        if (hi > lo) {
            unsigned int hm = (hi == 32) ? 0xFFFFFFFFu : ((1u << hi) - 1u);
            wmask = hm & (0xFFFFFFFFu << lo);
        }
        s_xm[ctid * STRIDE + wi] = wmask;
    }

    int ya = iy1 < row0 ? row0 : iy1;
    int yb = iy2 > row0 + HB ? row0 + HB : iy2;
    if (valid) {
        unsigned int  bit = 1u << (ctid & 31);
        unsigned int* tgt = (ctid < 32) ? s_lo : s_hi;
        for (int r = ya; r < yb; r++) atomicOr(&tgt[r - row0], bit);
    }
    // marking -> rows ordered by the block-wide __syncthreads in the kernel
}

// Count rows pass (warps 6-7 only): ffs-driven OR of x-masks, popcount.
template <int H, int W, int HB>
__device__ __forceinline__ unsigned int count_rows(unsigned int* sb) {
    constexpr int NW     = (W + 31) / 32;
    constexpr int STRIDE = (NW | 1);

    unsigned int* s_xm = sb;
    unsigned int* s_lo = sb + NBOX * STRIDE;
    unsigned int* s_hi = s_lo + HB;
    int ctid = threadIdx.x - 192;

    unsigned int cnt = 0;
    for (int rr = ctid; rr < HB; rr += 64) {
        unsigned int w[NW];
#pragma unroll
        for (int wi = 0; wi < NW; wi++) w[wi] = 0u;
        unsigned int mlo = s_lo[rr];
        unsigned int mhi = s_hi[rr];
        while (mlo) {
            int m = __ffs(mlo) - 1;
            mlo &= mlo - 1;
            const unsigned int* bm = &s_xm[m * STRIDE];
#pragma unroll
            for (int wi = 0; wi < NW; wi++) w[wi] |= bm[wi];
        }
        while (mhi) {
            int m = __ffs(mhi) - 1 + 32;
            mhi &= mhi - 1;
            const unsigned int* bm = &s_xm[m * STRIDE];
#pragma unroll
            for (int wi = 0; wi < NW; wi++) w[wi] |= bm[wi];
        }
#pragma unroll
        for (int wi = 0; wi < NW; wi++) cnt += (unsigned)__popc(w[wi]);
    }
    return cnt;
}

// ---------------------------------------------------------------------------
__global__ void __launch_bounds__(THREADS, 8)
work_kernel(const float* __restrict__ h0, const float* __restrict__ h1,
            const float* __restrict__ h2, const float* __restrict__ h3,
            const float* __restrict__ h4, const float* __restrict__ boxes,
            float* __restrict__ out) {
    __shared__ float        s_wsum[NWARP];
    __shared__ int          s_wlev[NWARP];
    __shared__ unsigned int s_cw[2];
    __shared__ unsigned int sb[800];   // count scratch (<=782 u32 used)

    int bx   = blockIdx.x;
    int tid  = threadIdx.x;
    int lane = tid & 31;
    int wid  = tid >> 5;

    bool is_cnt_blk  = (bx < CNT_BLOCKS);
    bool is_cnt_warp = is_cnt_blk && (wid >= 6);

    // count-task geometry (valid only for count blocks)
    int clev = 0, cb = 0, crow0 = 0;
    if (is_cnt_blk) {
        if (bx < 256) { clev = 0; cb = bx >> 1; crow0 = (bx & 1) * 167; }
        else {
            int t = bx - 256;
            clev  = 1 + (t >> 7);
            cb    = t & 127;
        }
    }

    // ========== phase A: sum warps load+reduce | count warps setup =========
    if (!is_cnt_warp) {
        int g = is_cnt_blk ? (bx * 6 + wid)
                           : (PURE_G_BASE + (bx - CNT_BLOCKS) * NWARP + wid);
        float s = 0.0f;
        int lev = -1;
        if (g < WSE) {
            lev = (g < WS1) ? 0 : (g < WS2) ? 1 : (g < WS3) ? 2
                : (g < WS4) ? 3 : 4;
            const float* hp = (lev == 0) ? h0 : (lev == 1) ? h1
                            : (lev == 2) ? h2 : (lev == 3) ? h3 : h4;
            int start = (lev == 0) ? WS0 : (lev == 1) ? WS1
                      : (lev == 2) ? WS2 : (lev == 3) ? WS3 : WS4;
            int n4    = (lev == 0) ? N4_0 : (lev == 1) ? N4_1
                      : (lev == 2) ? N4_2 : (lev == 3) ? N4_3 : N4_4;
            const float4* p = reinterpret_cast<const float4*>(hp);
            int idx0 = (g - start) * SPAN + lane;
            float a0 = 0.0f, a1 = 0.0f, a2 = 0.0f, a3 = 0.0f;
#pragma unroll
            for (int u = 0; u < ULOADS; u += 2) {
                int i0 = idx0 + u * 32;
                int i1 = idx0 + (u + 1) * 32;
                float4 v0 = (i0 < n4) ? p[i0] : make_float4(0.f, 0.f, 0.f, 0.f);
                float4 v1 = (i1 < n4) ? p[i1] : make_float4(0.f, 0.f, 0.f, 0.f);
                a0 += v0.x + v0.y;
                a1 += v0.z + v0.w;
                a2 += v1.x + v1.y;
                a3 += v1.z + v1.w;
            }
            s = (a0 + a1) + (a2 + a3);
#pragma unroll
            for (int o = 16; o > 0; o >>= 1)
                s += __shfl_down_sync(0xffffffffu, s, o);
        }
        if (lane == 0) { s_wsum[wid] = s; s_wlev[wid] = lev; }
    } else {
        switch (clev) {
            case 0:  count_setup<334, 200, 167>(
                         reinterpret_cast<const float4*>(boxes), cb, crow0, sb);
                     break;
            case 1:  count_setup<167, 100, 167>(
                         reinterpret_cast<const float4*>(boxes), cb, 0, sb);
                     break;
            case 2:  count_setup<84, 50, 84>(
                         reinterpret_cast<const float4*>(boxes), cb, 0, sb);
                     break;
            case 3:  count_setup<42, 25, 42>(
                         reinterpret_cast<const float4*>(boxes), cb, 0, sb);
                     break;
            default: count_setup<21, 13, 21>(
                         reinterpret_cast<const float4*>(boxes), cb, 0, sb);
                     break;
        }
    }
    __syncthreads();

    // ========== phase B: thread 0 combines sums | count warps do rows ======
    if (tid == 0) {
        int ns = is_cnt_blk ? 6 : NWARP;
        float acc0 = 0.f, acc1 = 0.f, acc2 = 0.f, acc3 = 0.f, acc4 = 0.f;
        for (int w2 = 0; w2 < ns; w2++) {
            int   l = s_wlev[w2];
            float v = s_wsum[w2];
            acc0 += (l == 0) ? v : 0.f;
            acc1 += (l == 1) ? v : 0.f;
            acc2 += (l == 2) ? v : 0.f;
            acc3 += (l == 3) ? v : 0.f;
            acc4 += (l == 4) ? v : 0.f;
        }
        float* ps = reinterpret_cast<float*>(&p_sum4[0][0]);
        ps[0 * TOTAL_BLOCKS + bx] = acc0;
        ps[1 * TOTAL_BLOCKS + bx] = acc1;
        ps[2 * TOTAL_BLOCKS + bx] = acc2;
        ps[3 * TOTAL_BLOCKS + bx] = acc3;
        ps[4 * TOTAL_BLOCKS + bx] = acc4;
    }
    if (is_cnt_warp) {
        unsigned int cnt;
        switch (clev) {
            case 0:  cnt = count_rows<334, 200, 167>(sb); break;
            case 1:  cnt = count_rows<167, 100, 167>(sb); break;
            case 2:  cnt = count_rows<84, 50, 84>(sb);    break;
            case 3:  cnt = count_rows<42, 25, 42>(sb);    break;
            default: cnt = count_rows<21, 13, 21>(sb);    break;
        }
#pragma unroll
        for (int o = 16; o > 0; o >>= 1)
            cnt += __shfl_down_sync(0xffffffffu, cnt, o);
        if (lane == 0) s_cw[wid - 6] = cnt;
    }
    __syncthreads();

    if (is_cnt_blk && tid == 0)
        reinterpret_cast<unsigned int*>(&p_cnt4[0])[bx] = s_cw[0] + s_cw[1];

    // ========== completion ticket -> finalize ==============================
    __shared__ bool is_last;
    __threadfence();
    if (tid == 0) {
        unsigned int v = atomicAdd(&g_done, 1u);
        is_last = (v == TOTAL_BLOCKS - 1);
    }
    __syncthreads();
    if (!is_last) return;
    __threadfence();

    __shared__ double s_d2[NLEV];
    if (wid < NLEV) {
        int lev = wid;
        double s = 0.0;
        for (int i = lane; i < PS_W; i += 32) {
            float4 v = p_sum4[lev][i];
            s += (double)((v.x + v.y) + (v.z + v.w));
        }
        unsigned int c = 0;
        if (lev == 0) {
            for (int i = lane; i < 64; i += 32) {
                uint4 v = p_cnt4[i];
                c += v.x + v.y + v.z + v.w;
            }
        } else {
            int base = 64 + (lev - 1) * 32;
            uint4 v = p_cnt4[base + lane];
            c += v.x + v.y + v.z + v.w;
        }
#pragma unroll
        for (int o = 16; o > 0; o >>= 1) {
            s += __shfl_down_sync(0xffffffffu, s, o);
            c += __shfl_down_sync(0xffffffffu, c, o);
        }
        if (lane == 0) {
            double tn = (double)BATCH * (double)c_Hc[lev] * (double)c_Wc[lev];
            double d  = s / tn - (double)c / tn;
            s_d2[lev] = d * d;
        }
    }
    __syncthreads();
    if (tid == 0) {
        double acc = s_d2[0] + s_d2[1] + s_d2[2] + s_d2[3] + s_d2[4];
        out[0] = (float)(acc / (double)NLEV);
        atomicExch(&g_done, 0u);
    }
}

// ---------------------------------------------------------------------------
extern "C" void kernel_launch(void* const* d_in, const int* in_sizes, int n_in,
                              void* d_out, int out_size) {
    (void)in_sizes; (void)n_in; (void)out_size;
    const float* h0    = (const float*)d_in[0];
    const float* h1    = (const float*)d_in[1];
    const float* h2    = (const float*)d_in[2];
    const float* h3    = (const float*)d_in[3];
    const float* h4    = (const float*)d_in[4];
    const float* boxes = (const float*)d_in[5];
    float* out = (float*)d_out;

    work_kernel<<<TOTAL_BLOCKS, THREADS>>>(h0, h1, h2, h3, h4, boxes, out);
}

// round 15
// speedup vs baseline: 1.2546x; 1.0118x over previous
#include <cuda_runtime.h>
#include <cstdint>

#define NLEV 5
#define BATCH 128
#define NBOX 64

static __constant__ int c_Hc[NLEV] = {334, 167, 84, 42, 21};
static __constant__ int c_Wc[NLEV] = {200, 100, 50, 25, 13};

// float4 counts per level: (128*H*W)/4
#define N4_0 2137600
#define N4_1 534400
#define N4_2 134400
#define N4_3 33600
#define N4_4 8736

// Exact warp partition (no predication anywhere):
//   L0: 4175 warps x 512 f4   (2137600 = 4175*512)
//   L1: 1670 warps x 320 f4   (534400 = 1670*320)
//   L2:  420 warps x 320 f4
//   L3:  105 warps x 320 f4
//   L4:   27 warps x 320 f4 + 1 tail warp x 96 f4 (3 lane-loads)
#define LA 4175
#define LB 5845
#define LC 6265
#define LD 6370
#define LE 6397          // tail warp id
#define NSUMW 6398

// Count blocks: level 0 split into 2 half-height tasks per batch.
#define CNT_BLOCKS   768
#define TOTAL_BLOCKS 1184            // one full wave at 8 blocks/SM
#define THREADS      256
#define NWARP        8
#define PS_W         296             // TOTAL_BLOCKS/4 float4 per level
#define PURE_G_BASE  (CNT_BLOCKS * 6)   // 4608

__device__ float4       p_sum4[NLEV][PS_W];
__device__ uint4        p_cnt4[CNT_BLOCKS / 4];
__device__ unsigned int g_done;   // zero at load; reset by last block

// ---------------------------------------------------------------------------
// Unpredicated span sum with L2::256B prefetch hint (non-coherent path).
// ---------------------------------------------------------------------------
__device__ __forceinline__ float4 ldg_nc_256(const float4* __restrict__ ap) {
    float4 v;
    asm("ld.global.nc.L2::256B.v4.f32 {%0,%1,%2,%3}, [%4];"
        : "=f"(v.x), "=f"(v.y), "=f"(v.z), "=f"(v.w) : "l"(ap));
    return v;
}

template <int U>
__device__ __forceinline__ float span_sum(const float4* __restrict__ p,
                                          int base, int lane) {
    float a0 = 0.f, a1 = 0.f, a2 = 0.f, a3 = 0.f;
#pragma unroll
    for (int u = 0; u < U; u++) {
        float4 v = ldg_nc_256(p + base + u * 32 + lane);
        float t = (v.x + v.y) + (v.z + v.w);
        switch (u & 3) {
            case 0: a0 += t; break;
            case 1: a1 += t; break;
            case 2: a2 += t; break;
            default: a3 += t; break;
        }
    }
    return (a0 + a1) + (a2 + a3);
}

// ---------------------------------------------------------------------------
// Count setup (warps 6-7 only, 64 threads): per-box x-masks + row marking.
// sb (u32): x-masks [64*STRIDE] | act_lo[HB] | act_hi[HB]
// ---------------------------------------------------------------------------
template <int H, int W, int HB>
__device__ __forceinline__ void count_setup(const float4* __restrict__ boxes4,
                                            int b, int row0, unsigned int* sb) {
    constexpr int   NW     = (W + 31) / 32;
    constexpr int   STRIDE = (NW | 1);
    constexpr float sx     = (float)(W / 800.0);
    constexpr float sy     = (float)(H / 1333.0);

    unsigned int* s_xm = sb;
    unsigned int* s_lo = sb + NBOX * STRIDE;
    unsigned int* s_hi = s_lo + HB;
    int ctid = threadIdx.x - 192;            // 0..63

    for (int i = ctid; i < 2 * HB; i += 64) s_lo[i] = 0u;
    asm volatile("bar.sync 1, 64;" ::: "memory");   // warps 6+7 only

    float4 bp = boxes4[b * NBOX + ctid];
    float fx1 = fminf(fmaxf(rintf(bp.x * sx), 0.0f), (float)(W - 1));
    float fy1 = fminf(fmaxf(rintf(bp.y * sy), 0.0f), (float)(H - 1));
    float fx2 = fminf(fmaxf(rintf(bp.z * sx), 0.0f), (float)W);
    float fy2 = fminf(fmaxf(rintf(bp.w * sy), 0.0f), (float)H);
    int ix1 = (int)fx1, iy1 = (int)fy1, ix2 = (int)fx2, iy2 = (int)fy2;
    bool valid = (fx2 > fx1) && (fy2 > fy1);

#pragma unroll
    for (int wi = 0; wi < NW; wi++) {
        int lo = ix1 - wi * 32;
        int hi = ix2 - wi * 32;
        lo = lo < 0 ? 0 : lo;
        hi = hi > 32 ? 32 : hi;
        unsigned int wmask = 0u;
        if (hi > lo) {
            unsigned int hm = (hi == 32) ? 0xFFFFFFFFu : ((1u << hi) - 1u);
            wmask = hm & (0xFFFFFFFFu << lo);
        }
        s_xm[ctid * STRIDE + wi] = wmask;
    }

    int ya = iy1 < row0 ? row0 : iy1;
    int yb = iy2 > row0 + HB ? row0 + HB : iy2;
    if (valid) {
        unsigned int  bit = 1u << (ctid & 31);
        unsigned int* tgt = (ctid < 32) ? s_lo : s_hi;
        for (int r = ya; r < yb; r++) atomicOr(&tgt[r - row0], bit);
    }
}

// Count rows pass (warps 6-7 only): ffs-driven OR of x-masks, popcount.
template <int H, int W, int HB>
__device__ __forceinline__ unsigned int count_rows(unsigned int* sb) {
    constexpr int NW     = (W + 31) / 32;
    constexpr int STRIDE = (NW | 1);

    unsigned int* s_xm = sb;
    unsigned int* s_lo = sb + NBOX * STRIDE;
    unsigned int* s_hi = s_lo + HB;
    int ctid = threadIdx.x - 192;

    unsigned int cnt = 0;
    for (int rr = ctid; rr < HB; rr += 64) {
        unsigned int w[NW];
#pragma unroll
        for (int wi = 0; wi < NW; wi++) w[wi] = 0u;
        unsigned int mlo = s_lo[rr];
        unsigned int mhi = s_hi[rr];
        while (mlo) {
            int m = __ffs(mlo) - 1;
            mlo &= mlo - 1;
            const unsigned int* bm = &s_xm[m * STRIDE];
#pragma unroll
            for (int wi = 0; wi < NW; wi++) w[wi] |= bm[wi];
        }
        while (mhi) {
            int m = __ffs(mhi) - 1 + 32;
            mhi &= mhi - 1;
            const unsigned int* bm = &s_xm[m * STRIDE];
#pragma unroll
            for (int wi = 0; wi < NW; wi++) w[wi] |= bm[wi];
        }
#pragma unroll
        for (int wi = 0; wi < NW; wi++) cnt += (unsigned)__popc(w[wi]);
    }
    return cnt;
}

// ---------------------------------------------------------------------------
__global__ void __launch_bounds__(THREADS, 8)
work_kernel(const float* __restrict__ h0, const float* __restrict__ h1,
            const float* __restrict__ h2, const float* __restrict__ h3,
            const float* __restrict__ h4, const float* __restrict__ boxes,
            float* __restrict__ out) {
    __shared__ float        s_wsum[NWARP];
    __shared__ int          s_wlev[NWARP];
    __shared__ unsigned int s_cw[2];
    __shared__ unsigned int sb[800];

    int bx   = blockIdx.x;
    int tid  = threadIdx.x;
    int lane = tid & 31;
    int wid  = tid >> 5;

    bool is_cnt_blk  = (bx < CNT_BLOCKS);
    bool is_cnt_warp = is_cnt_blk && (wid >= 6);

    int clev = 0, cb = 0, crow0 = 0;
    if (is_cnt_blk) {
        if (bx < 256) { clev = 0; cb = bx >> 1; crow0 = (bx & 1) * 167; }
        else {
            int t = bx - 256;
            clev  = 1 + (t >> 7);
            cb    = t & 127;
        }
    }

    // ========== phase A: sum warps load+reduce | count warps setup =========
    if (!is_cnt_warp) {
        int g = is_cnt_blk ? (bx * 6 + wid)
                           : (PURE_G_BASE + (bx - CNT_BLOCKS) * NWARP + wid);
        float s = 0.0f;
        int lev = -1;
        if (g < NSUMW) {
            if (g < LA) {
                lev = 0;
                s = span_sum<16>(reinterpret_cast<const float4*>(h0),
                                 g * 512, lane);
            } else if (g < LB) {
                lev = 1;
                s = span_sum<10>(reinterpret_cast<const float4*>(h1),
                                 (g - LA) * 320, lane);
            } else if (g < LC) {
                lev = 2;
                s = span_sum<10>(reinterpret_cast<const float4*>(h2),
                                 (g - LB) * 320, lane);
            } else if (g < LD) {
                lev = 3;
                s = span_sum<10>(reinterpret_cast<const float4*>(h3),
                                 (g - LC) * 320, lane);
            } else if (g < LE) {
                lev = 4;
                s = span_sum<10>(reinterpret_cast<const float4*>(h4),
                                 (g - LD) * 320, lane);
            } else {
                lev = 4;
                s = span_sum<3>(reinterpret_cast<const float4*>(h4),
                                27 * 320, lane);   // last 96 float4 of level 4
            }
#pragma unroll
            for (int o = 16; o > 0; o >>= 1)
                s += __shfl_down_sync(0xffffffffu, s, o);
        }
        if (lane == 0) { s_wsum[wid] = s; s_wlev[wid] = lev; }
    } else {
        switch (clev) {
            case 0:  count_setup<334, 200, 167>(
                         reinterpret_cast<const float4*>(boxes), cb, crow0, sb);
                     break;
            case 1:  count_setup<167, 100, 167>(
                         reinterpret_cast<const float4*>(boxes), cb, 0, sb);
                     break;
            case 2:  count_setup<84, 50, 84>(
                         reinterpret_cast<const float4*>(boxes), cb, 0, sb);
                     break;
            case 3:  count_setup<42, 25, 42>(
                         reinterpret_cast<const float4*>(boxes), cb, 0, sb);
                     break;
            default: count_setup<21, 13, 21>(
                         reinterpret_cast<const float4*>(boxes), cb, 0, sb);
                     break;
        }
    }
    __syncthreads();

    // ========== phase B: thread 0 combines sums | count warps do rows ======
    if (tid == 0) {
        int ns = is_cnt_blk ? 6 : NWARP;
        float acc0 = 0.f, acc1 = 0.f, acc2 = 0.f, acc3 = 0.f, acc4 = 0.f;
        for (int w2 = 0; w2 < ns; w2++) {
            int   l = s_wlev[w2];
            float v = s_wsum[w2];
            acc0 += (l == 0) ? v : 0.f;
            acc1 += (l == 1) ? v : 0.f;
            acc2 += (l == 2) ? v : 0.f;
            acc3 += (l == 3) ? v : 0.f;
            acc4 += (l == 4) ? v : 0.f;
        }
        float* ps = reinterpret_cast<float*>(&p_sum4[0][0]);
        ps[0 * TOTAL_BLOCKS + bx] = acc0;
        ps[1 * TOTAL_BLOCKS + bx] = acc1;
        ps[2 * TOTAL_BLOCKS + bx] = acc2;
        ps[3 * TOTAL_BLOCKS + bx] = acc3;
        ps[4 * TOTAL_BLOCKS + bx] = acc4;
    }
    if (is_cnt_warp) {
        unsigned int cnt;
        switch (clev) {
            case 0:  cnt = count_rows<334, 200, 167>(sb); break;
            case 1:  cnt = count_rows<167, 100, 167>(sb); break;
            case 2:  cnt = count_rows<84, 50, 84>(sb);    break;
            case 3:  cnt = count_rows<42, 25, 42>(sb);    break;
            default: cnt = count_rows<21, 13, 21>(sb);    break;
        }
#pragma unroll
        for (int o = 16; o > 0; o >>= 1)
            cnt += __shfl_down_sync(0xffffffffu, cnt, o);
        if (lane == 0) s_cw[wid - 6] = cnt;
    }
    __syncthreads();

    if (is_cnt_blk && tid == 0)
        reinterpret_cast<unsigned int*>(&p_cnt4[0])[bx] = s_cw[0] + s_cw[1];

    // ========== completion ticket -> finalize ==============================
    __shared__ bool is_last;
    __threadfence();
    if (tid == 0) {
        unsigned int v = atomicAdd(&g_done, 1u);
        is_last = (v == TOTAL_BLOCKS - 1);
    }
    __syncthreads();
    if (!is_last) return;
    __threadfence();

    __shared__ double s_d2[NLEV];
    if (wid < NLEV) {
        int lev = wid;
        double s = 0.0;
        for (int i = lane; i < PS_W; i += 32) {
            float4 v = p_sum4[lev][i];
            s += (double)((v.x + v.y) + (v.z + v.w));
        }
        unsigned int c = 0;
        if (lev == 0) {
            for (int i = lane; i < 64; i += 32) {
                uint4 v = p_cnt4[i];
                c += v.x + v.y + v.z + v.w;
            }
        } else {
            int base = 64 + (lev - 1) * 32;
            uint4 v = p_cnt4[base + lane];
            c += v.x + v.y + v.z + v.w;
        }
#pragma unroll
        for (int o = 16; o > 0; o >>= 1) {
            s += __shfl_down_sync(0xffffffffu, s, o);
            c += __shfl_down_sync(0xffffffffu, c, o);
        }
        if (lane == 0) {
            double tn = (double)BATCH * (double)c_Hc[lev] * (double)c_Wc[lev];
            double d  = s / tn - (double)c / tn;
            s_d2[lev] = d * d;
        }
    }
    __syncthreads();
    if (tid == 0) {
        double acc = s_d2[0] + s_d2[1] + s_d2[2] + s_d2[3] + s_d2[4];
        out[0] = (float)(acc / (double)NLEV);
        atomicExch(&g_done, 0u);
    }
}

// ---------------------------------------------------------------------------
extern "C" void kernel_launch(void* const* d_in, const int* in_sizes, int n_in,
                              void* d_out, int out_size) {
    (void)in_sizes; (void)n_in; (void)out_size;
    const float* h0    = (const float*)d_in[0];
    const float* h1    = (const float*)d_in[1];
    const float* h2    = (const float*)d_in[2];
    const float* h3    = (const float*)d_in[3];
    const float* h4    = (const float*)d_in[4];
    const float* boxes = (const float*)d_in[5];
    float* out = (float*)d_out;

    work_kernel<<<TOTAL_BLOCKS, THREADS>>>(h0, h1, h2, h3, h4, boxes, out);
}

// round 16
// speedup vs baseline: 1.2568x; 1.0017x over previous
#include <cuda_runtime.h>
#include <cstdint>

#define NLEV 5
#define BATCH 128
#define NBOX 64

static __constant__ int c_Hc[NLEV] = {334, 167, 84, 42, 21};
static __constant__ int c_Wc[NLEV] = {200, 100, 50, 25, 13};

// float4 counts per level: (128*H*W)/4
// L0 2137600 | L1 534400 | L2 134400 | L3 33600 | L4 8736  (total 2848736)

// Count blocks: level 0 split into 2 half-height tasks per batch.
#define CNT_BLOCKS   768
#define TOTAL_BLOCKS 1184            // one full wave at 8 blocks/SM
#define THREADS      256
#define NWARP        8
#define PS_W         296             // TOTAL_BLOCKS/4 float4 per level

// Warp partition (all spans unpredicated, no level straddling):
//  count-block sum warps: 4608 warps x 8 loads (256 f4) on L0  -> covers 1,179,648
//  pure warps (3328):
//   q <  1871          : L0, off 1179648 + q*512, 16 loads  (exact to L0 end)
//   r1 = q-1871 < 1044 : L1, r1<1043: r1*512 x16 ; r1==1043: off 534016 x12
//   r2 = q-2915 <  263 : L2, r2< 262: r2*512 x16 ; r2== 262: off 134144 x8
//   r3 = q-3178 <   66 : L3, r3<  65: r3*512 x16 ; r3==  65: off  33280 x10
//   r4 = q-3244 <   18 : L4, r4<  17: r4*512 x16 ; r4==  17: off   8704 x1
//   else idle (66 warps)

__device__ float4       p_sum4[NLEV][PS_W];
__device__ uint4        p_cnt4[CNT_BLOCKS / 4];
__device__ unsigned int g_done;   // zero at load; reset by last block

// ---------------------------------------------------------------------------
__device__ __forceinline__ float4 ldg_nc_256(const float4* __restrict__ ap) {
    float4 v;
    asm("ld.global.nc.L2::256B.v4.f32 {%0,%1,%2,%3}, [%4];"
        : "=f"(v.x), "=f"(v.y), "=f"(v.z), "=f"(v.w) : "l"(ap));
    return v;
}

template <int U>
__device__ __forceinline__ float span_sum(const float4* __restrict__ p,
                                          int base, int lane) {
    float a0 = 0.f, a1 = 0.f, a2 = 0.f, a3 = 0.f;
#pragma unroll
    for (int u = 0; u < U; u++) {
        float4 v = ldg_nc_256(p + base + u * 32 + lane);
        float t = (v.x + v.y) + (v.z + v.w);
        switch (u & 3) {
            case 0: a0 += t; break;
            case 1: a1 += t; break;
            case 2: a2 += t; break;
            default: a3 += t; break;
        }
    }
    return (a0 + a1) + (a2 + a3);
}

// ---------------------------------------------------------------------------
// Count setup (warps 6-7 of count blocks, 64 threads): x-masks + row marking.
// sb (u32): x-masks [64*STRIDE] | act_lo[HB] | act_hi[HB]
// ---------------------------------------------------------------------------
template <int H, int W, int HB>
__device__ __forceinline__ void count_setup(const float4* __restrict__ boxes4,
                                            int b, int row0, unsigned int* sb) {
    constexpr int   NW     = (W + 31) / 32;
    constexpr int   STRIDE = (NW | 1);
    constexpr float sx     = (float)(W / 800.0);
    constexpr float sy     = (float)(H / 1333.0);

    unsigned int* s_xm = sb;
    unsigned int* s_lo = sb + NBOX * STRIDE;
    unsigned int* s_hi = s_lo + HB;
    int ctid = threadIdx.x - 192;            // 0..63

    for (int i = ctid; i < 2 * HB; i += 64) s_lo[i] = 0u;
    asm volatile("bar.sync 1, 64;" ::: "memory");   // warps 6+7 only

    float4 bp = boxes4[b * NBOX + ctid];
    float fx1 = fminf(fmaxf(rintf(bp.x * sx), 0.0f), (float)(W - 1));
    float fy1 = fminf(fmaxf(rintf(bp.y * sy), 0.0f), (float)(H - 1));
    float fx2 = fminf(fmaxf(rintf(bp.z * sx), 0.0f), (float)W);
    float fy2 = fminf(fmaxf(rintf(bp.w * sy), 0.0f), (float)H);
    int ix1 = (int)fx1, iy1 = (int)fy1, ix2 = (int)fx2, iy2 = (int)fy2;
    bool valid = (fx2 > fx1) && (fy2 > fy1);

#pragma unroll
    for (int wi = 0; wi < NW; wi++) {
        int lo = ix1 - wi * 32;
        int hi = ix2 - wi * 32;
        lo = lo < 0 ? 0 : lo;
        hi = hi > 32 ? 32 : hi;
        unsigned int wmask = 0u;
        if (hi > lo) {
            unsigned int hm = (hi == 32) ? 0xFFFFFFFFu : ((1u << hi) - 1u);
            wmask = hm & (0xFFFFFFFFu << lo);
        }
        s_xm[ctid * STRIDE + wi] = wmask;
    }

    int ya = iy1 < row0 ? row0 : iy1;
    int yb = iy2 > row0 + HB ? row0 + HB : iy2;
    if (valid) {
        unsigned int  bit = 1u << (ctid & 31);
        unsigned int* tgt = (ctid < 32) ? s_lo : s_hi;
        for (int r = ya; r < yb; r++) atomicOr(&tgt[r - row0], bit);
    }
}

template <int H, int W, int HB>
__device__ __forceinline__ unsigned int count_rows(unsigned int* sb) {
    constexpr int NW     = (W + 31) / 32;
    constexpr int STRIDE = (NW | 1);

    unsigned int* s_xm = sb;
    unsigned int* s_lo = sb + NBOX * STRIDE;
    unsigned int* s_hi = s_lo + HB;
    int ctid = threadIdx.x - 192;

    unsigned int cnt = 0;
    for (int rr = ctid; rr < HB; rr += 64) {
        unsigned int w[NW];
#pragma unroll
        for (int wi = 0; wi < NW; wi++) w[wi] = 0u;
        unsigned int mlo = s_lo[rr];
        unsigned int mhi = s_hi[rr];
        while (mlo) {
            int m = __ffs(mlo) - 1;
            mlo &= mlo - 1;
            const unsigned int* bm = &s_xm[m * STRIDE];
#pragma unroll
            for (int wi = 0; wi < NW; wi++) w[wi] |= bm[wi];
        }
        while (mhi) {
            int m = __ffs(mhi) - 1 + 32;
            mhi &= mhi - 1;
            const unsigned int* bm = &s_xm[m * STRIDE];
#pragma unroll
            for (int wi = 0; wi < NW; wi++) w[wi] |= bm[wi];
        }
#pragma unroll
        for (int wi = 0; wi < NW; wi++) cnt += (unsigned)__popc(w[wi]);
    }
    return cnt;
}

// ---------------------------------------------------------------------------
__global__ void __launch_bounds__(THREADS, 8)
work_kernel(const float* __restrict__ h0, const float* __restrict__ h1,
            const float* __restrict__ h2, const float* __restrict__ h3,
            const float* __restrict__ h4, const float* __restrict__ boxes,
            float* __restrict__ out) {
    __shared__ float        s_wsum[NWARP];
    __shared__ int          s_wlev[NWARP];
    __shared__ unsigned int s_cw[2];
    __shared__ unsigned int sb[800];

    int bx   = blockIdx.x;
    int tid  = threadIdx.x;
    int lane = tid & 31;
    int wid  = tid >> 5;

    bool is_cnt_blk  = (bx < CNT_BLOCKS);
    bool is_cnt_warp = is_cnt_blk && (wid >= 6);

    int clev = 0, cb = 0, crow0 = 0;
    if (is_cnt_blk) {
        if (bx < 256) { clev = 0; cb = bx >> 1; crow0 = (bx & 1) * 167; }
        else {
            int t = bx - 256;
            clev  = 1 + (t >> 7);
            cb    = t & 127;
        }
    }

    // ========== phase A: sum warps load+reduce | count warps setup =========
    if (!is_cnt_warp) {
        float s = 0.0f;
        int lev = -1;
        if (is_cnt_blk) {
            int g = bx * 6 + wid;            // 0..4607, all on level 0
            lev = 0;
            s = span_sum<8>(reinterpret_cast<const float4*>(h0), g * 256, lane);
        } else {
            int q = (bx - CNT_BLOCKS) * NWARP + wid;   // 0..3327
            if (q < 1871) {
                lev = 0;
                s = span_sum<16>(reinterpret_cast<const float4*>(h0),
                                 1179648 + q * 512, lane);
            } else if (q < 2915) {
                int r = q - 1871;
                lev = 1;
                if (r < 1043)
                    s = span_sum<16>(reinterpret_cast<const float4*>(h1),
                                     r * 512, lane);
                else
                    s = span_sum<12>(reinterpret_cast<const float4*>(h1),
                                     534016, lane);
            } else if (q < 3178) {
                int r = q - 2915;
                lev = 2;
                if (r < 262)
                    s = span_sum<16>(reinterpret_cast<const float4*>(h2),
                                     r * 512, lane);
                else
                    s = span_sum<8>(reinterpret_cast<const float4*>(h2),
                                    134144, lane);
            } else if (q < 3244) {
                int r = q - 3178;
                lev = 3;
                if (r < 65)
                    s = span_sum<16>(reinterpret_cast<const float4*>(h3),
                                     r * 512, lane);
                else
                    s = span_sum<10>(reinterpret_cast<const float4*>(h3),
                                     33280, lane);
            } else if (q < 3262) {
                int r = q - 3244;
                lev = 4;
                if (r < 17)
                    s = span_sum<16>(reinterpret_cast<const float4*>(h4),
                                     r * 512, lane);
                else
                    s = span_sum<1>(reinterpret_cast<const float4*>(h4),
                                    8704, lane);
            }
        }
        if (lev >= 0) {
#pragma unroll
            for (int o = 16; o > 0; o >>= 1)
                s += __shfl_down_sync(0xffffffffu, s, o);
        }
        if (lane == 0) { s_wsum[wid] = s; s_wlev[wid] = lev; }
    } else {
        switch (clev) {
            case 0:  count_setup<334, 200, 167>(
                         reinterpret_cast<const float4*>(boxes), cb, crow0, sb);
                     break;
            case 1:  count_setup<167, 100, 167>(
                         reinterpret_cast<const float4*>(boxes), cb, 0, sb);
                     break;
            case 2:  count_setup<84, 50, 84>(
                         reinterpret_cast<const float4*>(boxes), cb, 0, sb);
                     break;
            case 3:  count_setup<42, 25, 42>(
                         reinterpret_cast<const float4*>(boxes), cb, 0, sb);
                     break;
            default: count_setup<21, 13, 21>(
                         reinterpret_cast<const float4*>(boxes), cb, 0, sb);
                     break;
        }
    }
    __syncthreads();

    // ========== phase B: thread 0 combines sums | count warps do rows ======
    if (tid == 0) {
        int ns = is_cnt_blk ? 6 : NWARP;
        float acc0 = 0.f, acc1 = 0.f, acc2 = 0.f, acc3 = 0.f, acc4 = 0.f;
        for (int w2 = 0; w2 < ns; w2++) {
            int   l = s_wlev[w2];
            float v = s_wsum[w2];
            acc0 += (l == 0) ? v : 0.f;
            acc1 += (l == 1) ? v : 0.f;
            acc2 += (l == 2) ? v : 0.f;
            acc3 += (l == 3) ? v : 0.f;
            acc4 += (l == 4) ? v : 0.f;
        }
        float* ps = reinterpret_cast<float*>(&p_sum4[0][0]);
        ps[0 * TOTAL_BLOCKS + bx] = acc0;
        ps[1 * TOTAL_BLOCKS + bx] = acc1;
        ps[2 * TOTAL_BLOCKS + bx] = acc2;
        ps[3 * TOTAL_BLOCKS + bx] = acc3;
        ps[4 * TOTAL_BLOCKS + bx] = acc4;
    }
    if (is_cnt_warp) {
        unsigned int cnt;
        switch (clev) {
            case 0:  cnt = count_rows<334, 200, 167>(sb); break;
            case 1:  cnt = count_rows<167, 100, 167>(sb); break;
            case 2:  cnt = count_rows<84, 50, 84>(sb);    break;
            case 3:  cnt = count_rows<42, 25, 42>(sb);    break;
            default: cnt = count_rows<21, 13, 21>(sb);    break;
        }
#pragma unroll
        for (int o = 16; o > 0; o >>= 1)
            cnt += __shfl_down_sync(0xffffffffu, cnt, o);
        if (lane == 0) s_cw[wid - 6] = cnt;
    }
    __syncthreads();

    if (is_cnt_blk && tid == 0)
        reinterpret_cast<unsigned int*>(&p_cnt4[0])[bx] = s_cw[0] + s_cw[1];

    // ========== completion ticket -> finalize ==============================
    __shared__ bool is_last;
    __threadfence();
    if (tid == 0) {
        unsigned int v = atomicAdd(&g_done, 1u);
        is_last = (v == TOTAL_BLOCKS - 1);
    }
    __syncthreads();
    if (!is_last) return;
    __threadfence();

    __shared__ double s_d2[NLEV];
    if (wid < NLEV) {
        int lev = wid;
        double s = 0.0;
        for (int i = lane; i < PS_W; i += 32) {
            float4 v = p_sum4[lev][i];
            s += (double)((v.x + v.y) + (v.z + v.w));
        }
        unsigned int c = 0;
        if (lev == 0) {
            for (int i = lane; i < 64; i += 32) {
                uint4 v = p_cnt4[i];
                c += v.x + v.y + v.z + v.w;
            }
        } else {
            int base = 64 + (lev - 1) * 32;
            uint4 v = p_cnt4[base + lane];
            c += v.x + v.y + v.z + v.w;
        }
#pragma unroll
        for (int o = 16; o > 0; o >>= 1) {
            s += __shfl_down_sync(0xffffffffu, s, o);
            c += __shfl_down_sync(0xffffffffu, c, o);
        }
        if (lane == 0) {
            double tn = (double)BATCH * (double)c_Hc[lev] * (double)c_Wc[lev];
            double d  = s / tn - (double)c / tn;
            s_d2[lev] = d * d;
        }
    }
    __syncthreads();
    if (tid == 0) {
        double acc = s_d2[0] + s_d2[1] + s_d2[2] + s_d2[3] + s_d2[4];
        out[0] = (float)(acc / (double)NLEV);
        atomicExch(&g_done, 0u);
    }
}

// ---------------------------------------------------------------------------
extern "C" void kernel_launch(void* const* d_in, const int* in_sizes, int n_in,
                              void* d_out, int out_size) {
    (void)in_sizes; (void)n_in; (void)out_size;
    const float* h0    = (const float*)d_in[0];
    const float* h1    = (const float*)d_in[1];
    const float* h2    = (const float*)d_in[2];
    const float* h3    = (const float*)d_in[3];
    const float* h4    = (const float*)d_in[4];
    const float* boxes = (const float*)d_in[5];
    float* out = (float*)d_out;

    work_kernel<<<TOTAL_BLOCKS, THREADS>>>(h0, h1, h2, h3, h4, boxes, out);
}